// round 5
// baseline (speedup 1.0000x reference)
#include <cuda_runtime.h>
#include <cuda_bf16.h>
#include <cstdint>
#include <math.h>

#define BB 4
#define SS 1024
#define DD 1024
#define HH 16
#define DK 64
#define MM (BB*SS)   // 4096

// ---------------- scratch (__device__ globals; no allocation) ---------------
__device__ __nv_bfloat16 g_qh[(size_t)MM*DD];
__device__ __nv_bfloat16 g_ql[(size_t)MM*DD];
__device__ __nv_bfloat16 g_kh[(size_t)MM*DD];
__device__ __nv_bfloat16 g_kl[(size_t)MM*DD];
__device__ __nv_bfloat16 g_vh[(size_t)MM*DD];
__device__ __nv_bfloat16 g_vl[(size_t)MM*DD];
__device__ __nv_bfloat16 g_wqh[(size_t)DD*DD];
__device__ __nv_bfloat16 g_wql[(size_t)DD*DD];
__device__ __nv_bfloat16 g_wkh[(size_t)DD*DD];
__device__ __nv_bfloat16 g_wkl[(size_t)DD*DD];
__device__ __nv_bfloat16 g_wvh[(size_t)DD*DD];
__device__ __nv_bfloat16 g_wvl[(size_t)DD*DD];
__device__ __nv_bfloat16 g_woh[(size_t)DD*DD];
__device__ __nv_bfloat16 g_wol[(size_t)DD*DD];
__device__ __nv_bfloat16 g_Qh[(size_t)MM*DD];
__device__ __nv_bfloat16 g_Ql[(size_t)MM*DD];
__device__ __nv_bfloat16 g_Kh[(size_t)MM*DD];
__device__ __nv_bfloat16 g_Kl[(size_t)MM*DD];
__device__ __nv_bfloat16 g_Vh[(size_t)MM*DD];
__device__ __nv_bfloat16 g_Vl[(size_t)MM*DD];
__device__ __nv_bfloat16 g_Ch[(size_t)MM*DD];
__device__ __nv_bfloat16 g_Cl[(size_t)MM*DD];
__device__ float g_x[(size_t)MM*DD];
// split-softmax partials: [bh(64)][tblock(8)][warp(4)][row(1024)]
__device__ float g_pMax[(size_t)64*8*4*1024];
__device__ float g_pSum[(size_t)64*8*4*1024];
__device__ float g_rowMax[(size_t)64*1024];
__device__ float g_rowInv[(size_t)64*1024];

// ---------------- helpers ----------------------------------------------------
__device__ __forceinline__ uint32_t smem_u32(const void* ptr) {
    return (uint32_t)__cvta_generic_to_shared(ptr);
}
__device__ __forceinline__ void cpasync16(void* smemDst, const void* gsrc) {
    asm volatile("cp.async.cg.shared.global [%0], [%1], 16;"
                 :: "r"(smem_u32(smemDst)), "l"(gsrc));
}
__device__ __forceinline__ void ldsm4(uint32_t* dst, uint32_t addr) {
    asm volatile("ldmatrix.sync.aligned.m8n8.x4.shared.b16 {%0,%1,%2,%3},[%4];"
                 : "=r"(dst[0]), "=r"(dst[1]), "=r"(dst[2]), "=r"(dst[3]) : "r"(addr));
}
__device__ __forceinline__ void ldsm4t(uint32_t* dst, uint32_t addr) {
    asm volatile("ldmatrix.sync.aligned.m8n8.x4.trans.shared.b16 {%0,%1,%2,%3},[%4];"
                 : "=r"(dst[0]), "=r"(dst[1]), "=r"(dst[2]), "=r"(dst[3]) : "r"(addr));
}
__device__ __forceinline__ void mma16816(float* cc, const uint32_t* aa, const uint32_t* bb2) {
    asm volatile("mma.sync.aligned.m16n8k16.row.col.f32.bf16.bf16.f32 "
                 "{%0,%1,%2,%3},{%4,%5,%6,%7},{%8,%9},{%0,%1,%2,%3};"
                 : "+f"(cc[0]), "+f"(cc[1]), "+f"(cc[2]), "+f"(cc[3])
                 : "r"(aa[0]), "r"(aa[1]), "r"(aa[2]), "r"(aa[3]), "r"(bb2[0]), "r"(bb2[1]));
}
__device__ __forceinline__ void splitbf(float xin, __nv_bfloat16& ho, __nv_bfloat16& lo) {
    ho = __float2bfloat16(xin);
    lo = __float2bfloat16(xin - __bfloat162float(ho));
}
__device__ __forceinline__ float wredMax(float wv) {
#pragma unroll
    for (int wo = 16; wo; wo >>= 1) wv = fmaxf(wv, __shfl_xor_sync(0xffffffffu, wv, wo));
    return wv;
}
__device__ __forceinline__ float wredSum(float wv) {
#pragma unroll
    for (int wo = 16; wo; wo >>= 1) wv += __shfl_xor_sync(0xffffffffu, wv, wo);
    return wv;
}

// =============================================================================
// Merged split: up to 4 tensors of NELEM fp32 each -> bf16 hi/lo
// =============================================================================
struct SplitArgs {
    const float* src[4];
    __nv_bfloat16* dsth[4];
    __nv_bfloat16* dstl[4];
};

template<int NT, int NELEM>
__global__ __launch_bounds__(256) void split_multi(SplitArgs args)
{
    const int nF4 = NELEM / 4;
    int gi = blockIdx.x * 256 + threadIdx.x;
    const int gstride = gridDim.x * 256;
    for (; gi < NT * nF4; gi += gstride) {
        int ti = gi / nF4;
        int off4 = gi - ti * nF4;
        int ei = off4 * 4;
        float4 sv = *(const float4*)(args.src[ti] + ei);
        __nv_bfloat16 sh0, sh1, sh2, sh3, sl0, sl1, sl2, sl3;
        splitbf(sv.x, sh0, sl0); splitbf(sv.y, sh1, sl1);
        splitbf(sv.z, sh2, sl2); splitbf(sv.w, sh3, sl3);
        *(__nv_bfloat162*)(args.dsth[ti] + ei)     = __halves2bfloat162(sh0, sh1);
        *(__nv_bfloat162*)(args.dsth[ti] + ei + 2) = __halves2bfloat162(sh2, sh3);
        *(__nv_bfloat162*)(args.dstl[ti] + ei)     = __halves2bfloat162(sl0, sl1);
        *(__nv_bfloat162*)(args.dstl[ti] + ei + 2) = __halves2bfloat162(sl2, sl3);
    }
}

// =============================================================================
// GEMM: C = A[4096,1024] @ W^T (+bias) (+res).  A,W pre-split bf16 hi/lo.
// Block 128x128, BK=32, 2-stage cp.async, 8 warps, 3-pass MMA, 2 CTAs/SM.
// =============================================================================
#define GT_TILE 5120            // 128*40 elems per array
#define GT_STAGE (4*GT_TILE)    // elems per stage

__device__ __forceinline__ void gemm_fill(
    __nv_bfloat16* pool, int st, int tid, int m0, int n0, int kk,
    const __nv_bfloat16* __restrict__ Ah, const __nv_bfloat16* __restrict__ Al,
    const __nv_bfloat16* __restrict__ Wh, const __nv_bfloat16* __restrict__ Wl)
{
    __nv_bfloat16* base = pool + (size_t)st * GT_STAGE;
#pragma unroll
    for (int qq = 0; qq < 2; qq++) {
        int lin = tid + qq * 256;
        int srow = lin >> 2;
        int scol = (lin & 3) * 8;
        size_t offA = (size_t)(m0 + srow) * 1024 + kk + scol;
        size_t offW = (size_t)(n0 + srow) * 1024 + kk + scol;
        int sidx = srow * 40 + scol;
        cpasync16(base + 0 * GT_TILE + sidx, Ah + offA);
        cpasync16(base + 1 * GT_TILE + sidx, Al + offA);
        cpasync16(base + 2 * GT_TILE + sidx, Wh + offW);
        cpasync16(base + 3 * GT_TILE + sidx, Wl + offW);
    }
    asm volatile("cp.async.commit_group;");
}

template<int QKV_OUT, int ADD_RES>
__global__ __launch_bounds__(256, 2) void gemm_tc(
    const __nv_bfloat16* __restrict__ Ah,
    const __nv_bfloat16* __restrict__ Al,
    const __nv_bfloat16* __restrict__ Wh,
    const __nv_bfloat16* __restrict__ Wl,
    const float* __restrict__ bias,
    const float* __restrict__ res,
    __nv_bfloat16* __restrict__ Oh,
    __nv_bfloat16* __restrict__ Ol,
    float* __restrict__ Of)
{
    extern __shared__ __align__(16) __nv_bfloat16 gpool[];

    const int tid  = threadIdx.x;
    const int lane = tid & 31;
    const int wid  = tid >> 5;
    const int wm   = wid >> 2;   // 0..1
    const int wn   = wid & 3;    // 0..3
    const int m0   = blockIdx.y * 128;
    const int n0   = blockIdx.x * 128;

    float acc[4][4][4];
#pragma unroll
    for (int im = 0; im < 4; im++)
#pragma unroll
        for (int jn = 0; jn < 4; jn++)
#pragma unroll
            for (int qq = 0; qq < 4; qq++) acc[im][jn][qq] = 0.f;

    gemm_fill(gpool, 0, tid, m0, n0, 0, Ah, Al, Wh, Wl);

    for (int it = 0; it < 32; it++) {
        if (it + 1 < 32) {
            gemm_fill(gpool, (it + 1) & 1, tid, m0, n0, (it + 1) * 32, Ah, Al, Wh, Wl);
            asm volatile("cp.async.wait_group 1;");
        } else {
            asm volatile("cp.async.wait_group 0;");
        }
        __syncthreads();

        __nv_bfloat16* sb = gpool + (size_t)(it & 1) * GT_STAGE;
        __nv_bfloat16* sAh = sb + 0 * GT_TILE;
        __nv_bfloat16* sAl = sb + 1 * GT_TILE;
        __nv_bfloat16* sWh = sb + 2 * GT_TILE;
        __nv_bfloat16* sWl = sb + 3 * GT_TILE;

#pragma unroll
        for (int ks = 0; ks < 32; ks += 16) {
            uint32_t fAh[4][4], fAl[4][4], fBh[4][2], fBl[4][2];
#pragma unroll
            for (int mt = 0; mt < 4; mt++) {
                int ra = wm * 64 + mt * 16 + (lane & 15);
                int ca = ks + (lane >> 4) * 8;
                ldsm4(fAh[mt], smem_u32(sAh + ra * 40 + ca));
                ldsm4(fAl[mt], smem_u32(sAl + ra * 40 + ca));
            }
#pragma unroll
            for (int pp = 0; pp < 2; pp++) {
                int rb = wn * 32 + pp * 16 + ((lane >> 4) & 1) * 8 + (lane & 7);
                int cb = ks + ((lane >> 3) & 1) * 8;
                ldsm4(&fBh[2 * pp][0], smem_u32(sWh + rb * 40 + cb));
                ldsm4(&fBl[2 * pp][0], smem_u32(sWl + rb * 40 + cb));
            }
#pragma unroll
            for (int mt = 0; mt < 4; mt++)
#pragma unroll
                for (int nt = 0; nt < 4; nt++) {
                    mma16816(acc[mt][nt], fAh[mt], fBh[nt]);
                    mma16816(acc[mt][nt], fAh[mt], fBl[nt]);
                    mma16816(acc[mt][nt], fAl[mt], fBh[nt]);
                }
        }
        __syncthreads();
    }

    const int cg = lane >> 2;
    const int ct = lane & 3;
#pragma unroll
    for (int mt = 0; mt < 4; mt++)
#pragma unroll
        for (int nt = 0; nt < 4; nt++) {
            int nn = n0 + wn * 32 + nt * 8 + 2 * ct;
            float bv0 = bias[nn];
            float bv1 = bias[nn + 1];
#pragma unroll
            for (int hrow = 0; hrow < 2; hrow++) {
                int mmv = m0 + wm * 64 + mt * 16 + cg + hrow * 8;
                float ov0 = acc[mt][nt][hrow * 2 + 0] + bv0;
                float ov1 = acc[mt][nt][hrow * 2 + 1] + bv1;
                if (ADD_RES) {
                    float2 rres = *(const float2*)(res + (size_t)mmv * 1024 + nn);
                    ov0 += rres.x;
                    ov1 += rres.y;
                }
                if (QKV_OUT) {
                    int obi = mmv >> 10;
                    int osi = mmv & 1023;
                    int ohh = nn >> 6;
                    int odd = nn & 63;
                    size_t oidx = (((size_t)(obi * HH + ohh)) * SS + osi) * DK + odd;
                    __nv_bfloat16 zh0, zl0, zh1, zl1;
                    splitbf(ov0, zh0, zl0);
                    splitbf(ov1, zh1, zl1);
                    *(__nv_bfloat162*)(Oh + oidx) = __halves2bfloat162(zh0, zh1);
                    *(__nv_bfloat162*)(Ol + oidx) = __halves2bfloat162(zl0, zl1);
                } else {
                    *(float2*)(Of + (size_t)mmv * 1024 + nn) = make_float2(ov0, ov1);
                }
            }
        }
}

// =============================================================================
// Scores + mask + per-block softmax partials.
// S[s,t] = (Q.K)/8, masked (-1e30). Writes masked scores to attn, plus
// per (bh, tblock, warp) row partial max/sumexp over that warp's 32 columns.
// =============================================================================
#define SC_TILE 9216   // 128*72

__global__ __launch_bounds__(256, 2) void scores_tc(
    const __nv_bfloat16* __restrict__ Qh, const __nv_bfloat16* __restrict__ Ql,
    const __nv_bfloat16* __restrict__ Kh, const __nv_bfloat16* __restrict__ Kl,
    const unsigned char* __restrict__ mask,
    float* __restrict__ attn,
    float* __restrict__ pMax, float* __restrict__ pSum)
{
    extern __shared__ __align__(16) __nv_bfloat16 spool[];
    __nv_bfloat16* sQh = spool + 0 * SC_TILE;
    __nv_bfloat16* sQl = spool + 1 * SC_TILE;
    __nv_bfloat16* sKh = spool + 2 * SC_TILE;
    __nv_bfloat16* sKl = spool + 3 * SC_TILE;

    const int tid  = threadIdx.x;
    const int lane = tid & 31;
    const int wid  = tid >> 5;
    const int wm   = wid >> 2;
    const int wn   = wid & 3;
    const int bhid = blockIdx.z;
    const int bidx = bhid >> 4;
    const int s0   = blockIdx.y * 128;
    const int t0   = blockIdx.x * 128;
    const size_t baseH = (size_t)bhid * SS * DK;

#pragma unroll
    for (int qq = 0; qq < 4; qq++) {
        int lin = tid + qq * 256;
        int srow = lin >> 3;
        int scol = (lin & 7) * 8;
        size_t offQ = baseH + (size_t)(s0 + srow) * DK + scol;
        size_t offK = baseH + (size_t)(t0 + srow) * DK + scol;
        int sidx = srow * 72 + scol;
        cpasync16(sQh + sidx, Qh + offQ);
        cpasync16(sQl + sidx, Ql + offQ);
        cpasync16(sKh + sidx, Kh + offK);
        cpasync16(sKl + sidx, Kl + offK);
    }
    asm volatile("cp.async.commit_group;");
    asm volatile("cp.async.wait_group 0;");
    __syncthreads();

    float acc[4][4][4];
#pragma unroll
    for (int im = 0; im < 4; im++)
#pragma unroll
        for (int jn = 0; jn < 4; jn++)
#pragma unroll
            for (int qq = 0; qq < 4; qq++) acc[im][jn][qq] = 0.f;

#pragma unroll
    for (int ks = 0; ks < 64; ks += 16) {
        uint32_t fAh[4][4], fAl[4][4], fBh[4][2], fBl[4][2];
#pragma unroll
        for (int mt = 0; mt < 4; mt++) {
            int ra = wm * 64 + mt * 16 + (lane & 15);
            int ca = ks + (lane >> 4) * 8;
            ldsm4(fAh[mt], smem_u32(sQh + ra * 72 + ca));
            ldsm4(fAl[mt], smem_u32(sQl + ra * 72 + ca));
        }
#pragma unroll
        for (int pp = 0; pp < 2; pp++) {
            int rb = wn * 32 + pp * 16 + ((lane >> 4) & 1) * 8 + (lane & 7);
            int cb = ks + ((lane >> 3) & 1) * 8;
            ldsm4(&fBh[2 * pp][0], smem_u32(sKh + rb * 72 + cb));
            ldsm4(&fBl[2 * pp][0], smem_u32(sKl + rb * 72 + cb));
        }
#pragma unroll
        for (int mt = 0; mt < 4; mt++)
#pragma unroll
            for (int nt = 0; nt < 4; nt++) {
                mma16816(acc[mt][nt], fAh[mt], fBh[nt]);
                mma16816(acc[mt][nt], fAh[mt], fBl[nt]);
                mma16816(acc[mt][nt], fAl[mt], fBh[nt]);
            }
    }

    // ---- epilogue: mask, store, per-row partial max/sumexp over warp's 32 cols
    const int cg = lane >> 2;
    const int ct = lane & 3;
    const size_t pbase = ((size_t)(bhid * 8 + (t0 >> 7)) * 4 + wn) * 1024;
#pragma unroll
    for (int mt = 0; mt < 4; mt++) {
#pragma unroll
        for (int hrow = 0; hrow < 2; hrow++) {
            int mmv = s0 + wm * 64 + mt * 16 + cg + hrow * 8;
            const unsigned char* mrow = mask + ((size_t)(bidx * SS + mmv)) * SS;
            float rv[8];
#pragma unroll
            for (int nt = 0; nt < 4; nt++) {
                int nn = t0 + wn * 32 + nt * 8 + 2 * ct;
                float av0 = acc[mt][nt][hrow * 2 + 0] * 0.125f;
                float av1 = acc[mt][nt][hrow * 2 + 1] * 0.125f;
                uchar2 mk2 = *(const uchar2*)(mrow + nn);
                if (mk2.x) av0 = -1e30f;
                if (mk2.y) av1 = -1e30f;
                rv[nt * 2 + 0] = av0;
                rv[nt * 2 + 1] = av1;
                *(float2*)(attn + ((size_t)bhid * SS + mmv) * SS + nn) = make_float2(av0, av1);
            }
            float pm = rv[0];
#pragma unroll
            for (int uu = 1; uu < 8; uu++) pm = fmaxf(pm, rv[uu]);
            float psm = 0.f;
#pragma unroll
            for (int uu = 0; uu < 8; uu++) psm += expf(rv[uu] - pm);
            // combine across the 4 lanes of this row (ct = lane&3)
#pragma unroll
            for (int xo = 1; xo < 4; xo <<= 1) {
                float opm = __shfl_xor_sync(0xffffffffu, pm, xo);
                float ops = __shfl_xor_sync(0xffffffffu, psm, xo);
                float nm = fmaxf(pm, opm);
                psm = psm * expf(pm - nm) + ops * expf(opm - nm);
                pm = nm;
            }
            if (ct == 0) {
                pMax[pbase + mmv] = pm;
                pSum[pbase + mmv] = psm;
            }
        }
    }
}

// =============================================================================
// Row reduce: combine 32 partials per row -> rowMax, rowInv. 1 warp per row.
// =============================================================================
__global__ __launch_bounds__(256) void rowstats_kernel(
    const float* __restrict__ pMax, const float* __restrict__ pSum,
    float* __restrict__ rowMax, float* __restrict__ rowInv)
{
    const int warp = threadIdx.x >> 5;
    const int lane = threadIdx.x & 31;
    const int row  = blockIdx.x * 8 + warp;   // bh*1024 + s, total 65536
    const int bh   = row >> 10;
    const int sidx = row & 1023;
    size_t pidx = ((size_t)(bh * 32 + lane)) * 1024 + sidx;  // (bh,tb,wn) flattened = lane
    float pm = pMax[pidx];
    float ps = pSum[pidx];
    float gm = wredMax(pm);
    float contrib = ps * expf(pm - gm);
    float gs = wredSum(contrib);
    if (lane == 0) {
        rowMax[row] = gm;
        rowInv[row] = 1.0f / gs;
    }
}

// =============================================================================
// Context + softmax finalize: reads masked scores from attn, computes
// p = exp(s - rowMax) * rowInv, writes p back in place, and accumulates
// ctx[s,d] = sum_t p * V[t,d] via split MMA.
// =============================================================================
__global__ __launch_bounds__(256, 2) void context_tc(
    float* __restrict__ attn,
    const float* __restrict__ rowMax, const float* __restrict__ rowInv,
    const __nv_bfloat16* __restrict__ Vh, const __nv_bfloat16* __restrict__ Vl,
    __nv_bfloat16* __restrict__ Ch, __nv_bfloat16* __restrict__ Cl)
{
    __shared__ __align__(16) __nv_bfloat16 sPh[128][40];
    __shared__ __align__(16) __nv_bfloat16 sPl[128][40];
    __shared__ __align__(16) __nv_bfloat16 sVh[32][72];
    __shared__ __align__(16) __nv_bfloat16 sVl[32][72];

    const int tid  = threadIdx.x;
    const int lane = tid & 31;
    const int wid  = tid >> 5;
    const int wm   = wid >> 1;   // 0..3
    const int wn   = wid & 1;    // 0..1
    const int bhid = blockIdx.y;
    const int bidx = bhid >> 4;
    const int hidx = bhid & 15;
    const int s0   = blockIdx.x * 128;

    float acc[2][4][4];
#pragma unroll
    for (int im = 0; im < 2; im++)
#pragma unroll
        for (int jn = 0; jn < 4; jn++)
#pragma unroll
            for (int qq = 0; qq < 4; qq++) acc[im][jn][qq] = 0.f;

    for (int kt = 0; kt < SS; kt += 32) {
#pragma unroll
        for (int qq = 0; qq < 4; qq++) {
            int lin = tid + qq * 256;
            int srow = lin >> 3;
            int scol = (lin & 7) * 4;
            int grow = bhid * SS + s0 + srow;
            float rm = rowMax[grow];
            float ri = rowInv[grow];
            size_t aoff = (size_t)grow * SS + kt + scol;
            float4 pv = *(const float4*)(attn + aoff);
            pv.x = expf(pv.x - rm) * ri;
            pv.y = expf(pv.y - rm) * ri;
            pv.z = expf(pv.z - rm) * ri;
            pv.w = expf(pv.w - rm) * ri;
            *(float4*)(attn + aoff) = pv;
            __nv_bfloat16 ph0, ph1, ph2, ph3, pl0, pl1, pl2, pl3;
            splitbf(pv.x, ph0, pl0); splitbf(pv.y, ph1, pl1);
            splitbf(pv.z, ph2, pl2); splitbf(pv.w, ph3, pl3);
            *(__nv_bfloat162*)&sPh[srow][scol]     = __halves2bfloat162(ph0, ph1);
            *(__nv_bfloat162*)&sPh[srow][scol + 2] = __halves2bfloat162(ph2, ph3);
            *(__nv_bfloat162*)&sPl[srow][scol]     = __halves2bfloat162(pl0, pl1);
            *(__nv_bfloat162*)&sPl[srow][scol + 2] = __halves2bfloat162(pl2, pl3);
        }
        {
            int vrow = tid >> 3;
            int vcol = (tid & 7) * 8;
            size_t offV = ((size_t)bhid * SS + kt + vrow) * DK + vcol;
            *(uint4*)&sVh[vrow][vcol] = *(const uint4*)(Vh + offV);
            *(uint4*)&sVl[vrow][vcol] = *(const uint4*)(Vl + offV);
        }
        __syncthreads();

#pragma unroll
        for (int ks = 0; ks < 32; ks += 16) {
            uint32_t fAh[2][4], fAl[2][4], fBh[4][2], fBl[4][2];
#pragma unroll
            for (int mt = 0; mt < 2; mt++) {
                int ra = wm * 32 + mt * 16 + (lane & 15);
                int ca = ks + (lane >> 4) * 8;
                ldsm4(fAh[mt], smem_u32(&sPh[ra][ca]));
                ldsm4(fAl[mt], smem_u32(&sPl[ra][ca]));
            }
#pragma unroll
            for (int pp = 0; pp < 2; pp++) {
                int rb = ks + ((lane >> 3) & 1) * 8 + (lane & 7);
                int cb = wn * 32 + pp * 16 + (lane >> 4) * 8;
                ldsm4t(&fBh[2 * pp][0], smem_u32(&sVh[rb][cb]));
                ldsm4t(&fBl[2 * pp][0], smem_u32(&sVl[rb][cb]));
            }
#pragma unroll
            for (int mt = 0; mt < 2; mt++)
#pragma unroll
                for (int nt = 0; nt < 4; nt++) {
                    mma16816(acc[mt][nt], fAh[mt], fBh[nt]);
                    mma16816(acc[mt][nt], fAh[mt], fBl[nt]);
                    mma16816(acc[mt][nt], fAl[mt], fBh[nt]);
                }
        }
        __syncthreads();
    }

    const int cg = lane >> 2;
    const int ct = lane & 3;
#pragma unroll
    for (int mt = 0; mt < 2; mt++)
#pragma unroll
        for (int nt = 0; nt < 4; nt++) {
            int dd = wn * 32 + nt * 8 + 2 * ct;
#pragma unroll
            for (int hrow = 0; hrow < 2; hrow++) {
                int mmv = s0 + wm * 32 + mt * 16 + cg + hrow * 8;
                float ov0 = acc[mt][nt][hrow * 2 + 0];
                float ov1 = acc[mt][nt][hrow * 2 + 1];
                size_t oidx = ((size_t)(bidx * SS + mmv)) * DD + hidx * 64 + dd;
                __nv_bfloat16 zh0, zl0, zh1, zl1;
                splitbf(ov0, zh0, zl0);
                splitbf(ov1, zh1, zl1);
                *(__nv_bfloat162*)(Ch + oidx) = __halves2bfloat162(zh0, zh1);
                *(__nv_bfloat162*)(Cl + oidx) = __halves2bfloat162(zl0, zl1);
            }
        }
}

// =============================================================================
// LayerNorm: one block per row of 1024.
// =============================================================================
__global__ __launch_bounds__(256) void ln_kernel(
    const float* __restrict__ xin, const float* __restrict__ gamma,
    const float* __restrict__ beta, float* __restrict__ outp)
{
    __shared__ float sredA[8];
    __shared__ float sredB[8];
    const int row = blockIdx.x;
    const int tt = threadIdx.x;
    float4 lv = *(const float4*)(xin + (size_t)row * DD + tt * 4);

    float s1 = lv.x + lv.y + lv.z + lv.w;
    float s2 = lv.x * lv.x + lv.y * lv.y + lv.z * lv.z + lv.w * lv.w;
    s1 = wredSum(s1);
    s2 = wredSum(s2);
    if ((tt & 31) == 0) { sredA[tt >> 5] = s1; sredB[tt >> 5] = s2; }
    __syncthreads();
    if (tt < 32) {
        float ta = (tt < 8) ? sredA[tt] : 0.f;
        float tb = (tt < 8) ? sredB[tt] : 0.f;
        ta = wredSum(ta);
        tb = wredSum(tb);
        if (tt == 0) { sredA[0] = ta; sredB[0] = tb; }
    }
    __syncthreads();
    float mu  = sredA[0] * (1.0f / 1024.0f);
    float var = sredB[0] * (1.0f / 1024.0f) - mu * mu;
    float inv = rsqrtf(var + 1e-6f);

    float4 gv4 = *(const float4*)(gamma + tt * 4);
    float4 bv4 = *(const float4*)(beta + tt * 4);
    float4 ov4;
    ov4.x = (lv.x - mu) * inv * gv4.x + bv4.x;
    ov4.y = (lv.y - mu) * inv * gv4.y + bv4.y;
    ov4.z = (lv.z - mu) * inv * gv4.z + bv4.z;
    ov4.w = (lv.w - mu) * inv * gv4.w + bv4.w;
    *(float4*)(outp + (size_t)row * DD + tt * 4) = ov4;
}

// =============================================================================
extern "C" void kernel_launch(void* const* d_in, const int* in_sizes, int n_in,
                              void* d_out, int out_size)
{
    const float* in_q = (const float*)d_in[0];
    const float* in_k = (const float*)d_in[1];
    const float* in_v = (const float*)d_in[2];
    const unsigned char* in_mask = (const unsigned char*)d_in[3];
    const float* Wq   = (const float*)d_in[4];
    const float* bq   = (const float*)d_in[5];
    const float* Wk   = (const float*)d_in[6];
    const float* bk   = (const float*)d_in[7];
    const float* Wv   = (const float*)d_in[8];
    const float* bvv  = (const float*)d_in[9];
    const float* Wo   = (const float*)d_in[10];
    const float* bo   = (const float*)d_in[11];
    const float* ln_g = (const float*)d_in[12];
    const float* ln_b = (const float*)d_in[13];

    float* out_norm = (float*)d_out;
    float* attn = (float*)d_out + (size_t)MM * DD;

    __nv_bfloat16 *pqh, *pql, *pkh, *pkl, *pvh, *pvl;
    __nv_bfloat16 *pwqh, *pwql, *pwkh, *pwkl, *pwvh, *pwvl, *pwoh, *pwol;
    __nv_bfloat16 *pQh, *pQl, *pKh, *pKl, *pVh, *pVl, *pCh, *pCl;
    float *pX, *pPM, *pPS, *pRM, *pRI;
    cudaGetSymbolAddress((void**)&pqh, g_qh);
    cudaGetSymbolAddress((void**)&pql, g_ql);
    cudaGetSymbolAddress((void**)&pkh, g_kh);
    cudaGetSymbolAddress((void**)&pkl, g_kl);
    cudaGetSymbolAddress((void**)&pvh, g_vh);
    cudaGetSymbolAddress((void**)&pvl, g_vl);
    cudaGetSymbolAddress((void**)&pwqh, g_wqh);
    cudaGetSymbolAddress((void**)&pwql, g_wql);
    cudaGetSymbolAddress((void**)&pwkh, g_wkh);
    cudaGetSymbolAddress((void**)&pwkl, g_wkl);
    cudaGetSymbolAddress((void**)&pwvh, g_wvh);
    cudaGetSymbolAddress((void**)&pwvl, g_wvl);
    cudaGetSymbolAddress((void**)&pwoh, g_woh);
    cudaGetSymbolAddress((void**)&pwol, g_wol);
    cudaGetSymbolAddress((void**)&pQh, g_Qh);
    cudaGetSymbolAddress((void**)&pQl, g_Ql);
    cudaGetSymbolAddress((void**)&pKh, g_Kh);
    cudaGetSymbolAddress((void**)&pKl, g_Kl);
    cudaGetSymbolAddress((void**)&pVh, g_Vh);
    cudaGetSymbolAddress((void**)&pVl, g_Vl);
    cudaGetSymbolAddress((void**)&pCh, g_Ch);
    cudaGetSymbolAddress((void**)&pCl, g_Cl);
    cudaGetSymbolAddress((void**)&pX,  g_x);
    cudaGetSymbolAddress((void**)&pPM, g_pMax);
    cudaGetSymbolAddress((void**)&pPS, g_pSum);
    cudaGetSymbolAddress((void**)&pRM, g_rowMax);
    cudaGetSymbolAddress((void**)&pRI, g_rowInv);

    cudaFuncSetAttribute(gemm_tc<1, 0>, cudaFuncAttributeMaxDynamicSharedMemorySize, 81920);
    cudaFuncSetAttribute(gemm_tc<0, 1>, cudaFuncAttributeMaxDynamicSharedMemorySize, 81920);
    cudaFuncSetAttribute(scores_tc, cudaFuncAttributeMaxDynamicSharedMemorySize, 73728);

    SplitArgs sa;
    sa.src[0] = in_q;  sa.dsth[0] = pqh;  sa.dstl[0] = pql;
    sa.src[1] = in_k;  sa.dsth[1] = pkh;  sa.dstl[1] = pkl;
    sa.src[2] = in_v;  sa.dsth[2] = pvh;  sa.dstl[2] = pvl;
    sa.src[3] = in_q;  sa.dsth[3] = pqh;  sa.dstl[3] = pql;  // unused
    split_multi<3, MM * DD><<<2048, 256>>>(sa);

    SplitArgs sw;
    sw.src[0] = Wq;  sw.dsth[0] = pwqh;  sw.dstl[0] = pwql;
    sw.src[1] = Wk;  sw.dsth[1] = pwkh;  sw.dstl[1] = pwkl;
    sw.src[2] = Wv;  sw.dsth[2] = pwvh;  sw.dstl[2] = pwvl;
    sw.src[3] = Wo;  sw.dsth[3] = pwoh;  sw.dstl[3] = pwol;
    split_multi<4, DD * DD><<<2048, 256>>>(sw);

    dim3 gGemm(DD / 128, MM / 128);   // (8, 32)
    gemm_tc<1, 0><<<gGemm, 256, 81920>>>(pqh, pql, pwqh, pwql, bq, nullptr, pQh, pQl, nullptr);
    gemm_tc<1, 0><<<gGemm, 256, 81920>>>(pkh, pkl, pwkh, pwkl, bk, nullptr, pKh, pKl, nullptr);
    gemm_tc<1, 0><<<gGemm, 256, 81920>>>(pvh, pvl, pwvh, pwvl, bvv, nullptr, pVh, pVl, nullptr);

    dim3 gSc(SS / 128, SS / 128, BB * HH);   // (8,8,64)
    scores_tc<<<gSc, 256, 73728>>>(pQh, pQl, pKh, pKl, in_mask, attn, pPM, pPS);

    rowstats_kernel<<<(64 * 1024) / 8, 256>>>(pPM, pPS, pRM, pRI);

    dim3 gCtx(SS / 128, BB * HH);            // (8,64)
    context_tc<<<gCtx, 256>>>(attn, pRM, pRI, pVh, pVl, pCh, pCl);

    gemm_tc<0, 1><<<gGemm, 256, 81920>>>(pCh, pCl, pwoh, pwol, bo, in_v, nullptr, nullptr, pX);

    ln_kernel<<<MM, 256>>>(pX, ln_g, ln_b, out_norm);
}

// round 7
// speedup vs baseline: 1.0624x; 1.0624x over previous
#include <cuda_runtime.h>
#include <cuda_bf16.h>
#include <cstdint>
#include <math.h>

#define BB 4
#define SS 1024
#define DD 1024
#define HH 16
#define DK 64
#define MM (BB*SS)   // 4096

// ---------------- scratch (__device__ globals; no allocation) ---------------
__device__ __nv_bfloat16 g_qh[(size_t)MM*DD];
__device__ __nv_bfloat16 g_ql[(size_t)MM*DD];
__device__ __nv_bfloat16 g_kh[(size_t)MM*DD];
__device__ __nv_bfloat16 g_kl[(size_t)MM*DD];
__device__ __nv_bfloat16 g_vh[(size_t)MM*DD];
__device__ __nv_bfloat16 g_vl[(size_t)MM*DD];
__device__ __nv_bfloat16 g_wqh[(size_t)DD*DD];
__device__ __nv_bfloat16 g_wql[(size_t)DD*DD];
__device__ __nv_bfloat16 g_wkh[(size_t)DD*DD];
__device__ __nv_bfloat16 g_wkl[(size_t)DD*DD];
__device__ __nv_bfloat16 g_wvh[(size_t)DD*DD];
__device__ __nv_bfloat16 g_wvl[(size_t)DD*DD];
__device__ __nv_bfloat16 g_woh[(size_t)DD*DD];
__device__ __nv_bfloat16 g_wol[(size_t)DD*DD];
__device__ __nv_bfloat16 g_Qh[(size_t)MM*DD];
__device__ __nv_bfloat16 g_Ql[(size_t)MM*DD];
__device__ __nv_bfloat16 g_Kh[(size_t)MM*DD];
__device__ __nv_bfloat16 g_Kl[(size_t)MM*DD];
__device__ __nv_bfloat16 g_Vh[(size_t)MM*DD];
__device__ __nv_bfloat16 g_Vl[(size_t)MM*DD];
__device__ __nv_bfloat16 g_Ch[(size_t)MM*DD];
__device__ __nv_bfloat16 g_Cl[(size_t)MM*DD];
__device__ float g_x[(size_t)MM*DD];

// ---------------- helpers ----------------------------------------------------
__device__ __forceinline__ uint32_t smem_u32(const void* ptr) {
    return (uint32_t)__cvta_generic_to_shared(ptr);
}
__device__ __forceinline__ void cpasync16(void* smemDst, const void* gsrc) {
    asm volatile("cp.async.cg.shared.global [%0], [%1], 16;"
                 :: "r"(smem_u32(smemDst)), "l"(gsrc));
}
__device__ __forceinline__ void ldsm4(uint32_t* dst, uint32_t addr) {
    asm volatile("ldmatrix.sync.aligned.m8n8.x4.shared.b16 {%0,%1,%2,%3},[%4];"
                 : "=r"(dst[0]), "=r"(dst[1]), "=r"(dst[2]), "=r"(dst[3]) : "r"(addr));
}
__device__ __forceinline__ void ldsm4t(uint32_t* dst, uint32_t addr) {
    asm volatile("ldmatrix.sync.aligned.m8n8.x4.trans.shared.b16 {%0,%1,%2,%3},[%4];"
                 : "=r"(dst[0]), "=r"(dst[1]), "=r"(dst[2]), "=r"(dst[3]) : "r"(addr));
}
__device__ __forceinline__ void mma16816(float* cc, const uint32_t* aa, const uint32_t* bb2) {
    asm volatile("mma.sync.aligned.m16n8k16.row.col.f32.bf16.bf16.f32 "
                 "{%0,%1,%2,%3},{%4,%5,%6,%7},{%8,%9},{%0,%1,%2,%3};"
                 : "+f"(cc[0]), "+f"(cc[1]), "+f"(cc[2]), "+f"(cc[3])
                 : "r"(aa[0]), "r"(aa[1]), "r"(aa[2]), "r"(aa[3]), "r"(bb2[0]), "r"(bb2[1]));
}
__device__ __forceinline__ void splitbf(float xin, __nv_bfloat16& ho, __nv_bfloat16& lo) {
    ho = __float2bfloat16(xin);
    lo = __float2bfloat16(xin - __bfloat162float(ho));
}
__device__ __forceinline__ float wredSum(float wv) {
#pragma unroll
    for (int wo = 16; wo; wo >>= 1) wv += __shfl_xor_sync(0xffffffffu, wv, wo);
    return wv;
}

// =============================================================================
// Merged split: up to 4 tensors of NELEM fp32 each -> bf16 hi/lo
// =============================================================================
struct SplitArgs {
    const float* src[4];
    __nv_bfloat16* dsth[4];
    __nv_bfloat16* dstl[4];
};

template<int NT, int NELEM>
__global__ __launch_bounds__(256) void split_multi(SplitArgs args)
{
    const int nF4 = NELEM / 4;
    int gi = blockIdx.x * 256 + threadIdx.x;
    const int gstride = gridDim.x * 256;
    for (; gi < NT * nF4; gi += gstride) {
        int ti = gi / nF4;
        int off4 = gi - ti * nF4;
        int ei = off4 * 4;
        float4 sv = *(const float4*)(args.src[ti] + ei);
        __nv_bfloat16 sh0, sh1, sh2, sh3, sl0, sl1, sl2, sl3;
        splitbf(sv.x, sh0, sl0); splitbf(sv.y, sh1, sl1);
        splitbf(sv.z, sh2, sl2); splitbf(sv.w, sh3, sl3);
        *(__nv_bfloat162*)(args.dsth[ti] + ei)     = __halves2bfloat162(sh0, sh1);
        *(__nv_bfloat162*)(args.dsth[ti] + ei + 2) = __halves2bfloat162(sh2, sh3);
        *(__nv_bfloat162*)(args.dstl[ti] + ei)     = __halves2bfloat162(sl0, sl1);
        *(__nv_bfloat162*)(args.dstl[ti] + ei + 2) = __halves2bfloat162(sl2, sl3);
    }
}

// =============================================================================
// GEMM: C = A[4096,1024] @ W^T (+bias) (+res).  A,W pre-split bf16 hi/lo.
// Block 128x128, BK=32, 2-stage cp.async, 8 warps, pass-major 3-pass MMA.
// =============================================================================
#define GT_TILE 5120            // 128*40 elems per array
#define GT_STAGE (4*GT_TILE)    // elems per stage

__device__ __forceinline__ void gemm_fill(
    __nv_bfloat16* pool, int st, int tid, int m0, int n0, int kk,
    const __nv_bfloat16* __restrict__ Ah, const __nv_bfloat16* __restrict__ Al,
    const __nv_bfloat16* __restrict__ Wh, const __nv_bfloat16* __restrict__ Wl)
{
    __nv_bfloat16* base = pool + (size_t)st * GT_STAGE;
#pragma unroll
    for (int qq = 0; qq < 2; qq++) {
        int lin = tid + qq * 256;
        int srow = lin >> 2;
        int scol = (lin & 3) * 8;
        size_t offA = (size_t)(m0 + srow) * 1024 + kk + scol;
        size_t offW = (size_t)(n0 + srow) * 1024 + kk + scol;
        int sidx = srow * 40 + scol;
        cpasync16(base + 0 * GT_TILE + sidx, Ah + offA);
        cpasync16(base + 1 * GT_TILE + sidx, Al + offA);
        cpasync16(base + 2 * GT_TILE + sidx, Wh + offW);
        cpasync16(base + 3 * GT_TILE + sidx, Wl + offW);
    }
    asm volatile("cp.async.commit_group;");
}

template<int QKV_OUT, int ADD_RES>
__global__ __launch_bounds__(256) void gemm_tc(
    const __nv_bfloat16* __restrict__ Ah,
    const __nv_bfloat16* __restrict__ Al,
    const __nv_bfloat16* __restrict__ Wh,
    const __nv_bfloat16* __restrict__ Wl,
    const float* __restrict__ bias,
    const float* __restrict__ res,
    __nv_bfloat16* __restrict__ Oh,
    __nv_bfloat16* __restrict__ Ol,
    float* __restrict__ Of)
{
    extern __shared__ __align__(16) __nv_bfloat16 gpool[];

    const int tid  = threadIdx.x;
    const int lane = tid & 31;
    const int wid  = tid >> 5;
    const int wm   = wid >> 2;   // 0..1
    const int wn   = wid & 3;    // 0..3
    const int m0   = blockIdx.y * 128;
    const int n0   = blockIdx.x * 128;

    float acc[4][4][4];
#pragma unroll
    for (int im = 0; im < 4; im++)
#pragma unroll
        for (int jn = 0; jn < 4; jn++)
#pragma unroll
            for (int qq = 0; qq < 4; qq++) acc[im][jn][qq] = 0.f;

    gemm_fill(gpool, 0, tid, m0, n0, 0, Ah, Al, Wh, Wl);

    for (int it = 0; it < 32; it++) {
        if (it + 1 < 32) {
            gemm_fill(gpool, (it + 1) & 1, tid, m0, n0, (it + 1) * 32, Ah, Al, Wh, Wl);
            asm volatile("cp.async.wait_group 1;");
        } else {
            asm volatile("cp.async.wait_group 0;");
        }
        __syncthreads();

        __nv_bfloat16* sb = gpool + (size_t)(it & 1) * GT_STAGE;
        __nv_bfloat16* sAh = sb + 0 * GT_TILE;
        __nv_bfloat16* sAl = sb + 1 * GT_TILE;
        __nv_bfloat16* sWh = sb + 2 * GT_TILE;
        __nv_bfloat16* sWl = sb + 3 * GT_TILE;

#pragma unroll
        for (int ks = 0; ks < 32; ks += 16) {
            uint32_t fAh[4][4], fAl[4][4], fBh[4][2], fBl[4][2];
#pragma unroll
            for (int mt = 0; mt < 4; mt++) {
                int ra = wm * 64 + mt * 16 + (lane & 15);
                int ca = ks + (lane >> 4) * 8;
                ldsm4(fAh[mt], smem_u32(sAh + ra * 40 + ca));
                ldsm4(fAl[mt], smem_u32(sAl + ra * 40 + ca));
            }
#pragma unroll
            for (int pp = 0; pp < 2; pp++) {
                int rb = wn * 32 + pp * 16 + ((lane >> 4) & 1) * 8 + (lane & 7);
                int cb = ks + ((lane >> 3) & 1) * 8;
                ldsm4(&fBh[2 * pp][0], smem_u32(sWh + rb * 40 + cb));
                ldsm4(&fBl[2 * pp][0], smem_u32(sWl + rb * 40 + cb));
            }
            // pass-major issue order: same-acc revisit distance = 16 MMAs
#pragma unroll
            for (int mt = 0; mt < 4; mt++)
#pragma unroll
                for (int nt = 0; nt < 4; nt++)
                    mma16816(acc[mt][nt], fAh[mt], fBh[nt]);
#pragma unroll
            for (int mt = 0; mt < 4; mt++)
#pragma unroll
                for (int nt = 0; nt < 4; nt++)
                    mma16816(acc[mt][nt], fAh[mt], fBl[nt]);
#pragma unroll
            for (int mt = 0; mt < 4; mt++)
#pragma unroll
                for (int nt = 0; nt < 4; nt++)
                    mma16816(acc[mt][nt], fAl[mt], fBh[nt]);
        }
        __syncthreads();
    }

    const int cg = lane >> 2;
    const int ct = lane & 3;
#pragma unroll
    for (int mt = 0; mt < 4; mt++)
#pragma unroll
        for (int nt = 0; nt < 4; nt++) {
            int nn = n0 + wn * 32 + nt * 8 + 2 * ct;
            float bv0 = bias[nn];
            float bv1 = bias[nn + 1];
#pragma unroll
            for (int hrow = 0; hrow < 2; hrow++) {
                int mmv = m0 + wm * 64 + mt * 16 + cg + hrow * 8;
                float ov0 = acc[mt][nt][hrow * 2 + 0] + bv0;
                float ov1 = acc[mt][nt][hrow * 2 + 1] + bv1;
                if (ADD_RES) {
                    float2 rres = *(const float2*)(res + (size_t)mmv * 1024 + nn);
                    ov0 += rres.x;
                    ov1 += rres.y;
                }
                if (QKV_OUT) {
                    int obi = mmv >> 10;
                    int osi = mmv & 1023;
                    int ohh = nn >> 6;
                    int odd = nn & 63;
                    size_t oidx = (((size_t)(obi * HH + ohh)) * SS + osi) * DK + odd;
                    __nv_bfloat16 zh0, zl0, zh1, zl1;
                    splitbf(ov0, zh0, zl0);
                    splitbf(ov1, zh1, zl1);
                    *(__nv_bfloat162*)(Oh + oidx) = __halves2bfloat162(zh0, zh1);
                    *(__nv_bfloat162*)(Ol + oidx) = __halves2bfloat162(zl0, zl1);
                } else {
                    *(float2*)(Of + (size_t)mmv * 1024 + nn) = make_float2(ov0, ov1);
                }
            }
        }
}

// =============================================================================
// Fused scores + mask + softmax.
// One CTA owns a 128-row x 1024-col strip of one head. Loops 8 K-tiles with a
// 2-stage cp.async double buffer, writes masked raw scores, keeps online
// (max,sumexp) row stats in registers, then normalizes its strip in place.
// =============================================================================
#define SCF_TILE 9216   // 128*72 elems per array

__device__ __forceinline__ void scf_fillK(
    __nv_bfloat16* pool, int st, int tid, size_t baseH, int tt,
    const __nv_bfloat16* __restrict__ Kh, const __nv_bfloat16* __restrict__ Kl)
{
    __nv_bfloat16* dKh = pool + (2 + 2 * st) * SCF_TILE;
    __nv_bfloat16* dKl = dKh + SCF_TILE;
#pragma unroll
    for (int qq = 0; qq < 4; qq++) {
        int lin = tid + qq * 256;
        int srow = lin >> 3;
        int scol = (lin & 7) * 8;
        size_t offK = baseH + (size_t)(tt * 128 + srow) * DK + scol;
        int sidx = srow * 72 + scol;
        cpasync16(dKh + sidx, Kh + offK);
        cpasync16(dKl + sidx, Kl + offK);
    }
    asm volatile("cp.async.commit_group;");
}

__global__ __launch_bounds__(256) void scores_fused(
    const __nv_bfloat16* __restrict__ Qh, const __nv_bfloat16* __restrict__ Ql,
    const __nv_bfloat16* __restrict__ Kh, const __nv_bfloat16* __restrict__ Kl,
    const unsigned char* __restrict__ mask,
    float* __restrict__ attn)
{
    extern __shared__ __align__(16) __nv_bfloat16 spool[];
    __nv_bfloat16* sQh = spool + 0 * SCF_TILE;
    __nv_bfloat16* sQl = spool + 1 * SCF_TILE;
    __shared__ float warpM[4][128];
    __shared__ float warpL[4][128];
    __shared__ float rowM[128];
    __shared__ float rowI[128];

    const int tid  = threadIdx.x;
    const int lane = tid & 31;
    const int wid  = tid >> 5;
    const int wm   = wid >> 2;
    const int wn   = wid & 3;
    const int s0   = blockIdx.x * 128;
    const int bhid = blockIdx.y;
    const int bidx = bhid >> 4;
    const size_t baseH = (size_t)bhid * SS * DK;

    // prologue: Q (once) + K tile 0
#pragma unroll
    for (int qq = 0; qq < 4; qq++) {
        int lin = tid + qq * 256;
        int srow = lin >> 3;
        int scol = (lin & 7) * 8;
        size_t offQ = baseH + (size_t)(s0 + srow) * DK + scol;
        int sidx = srow * 72 + scol;
        cpasync16(sQh + sidx, Qh + offQ);
        cpasync16(sQl + sidx, Ql + offQ);
    }
    scf_fillK(spool, 0, tid, baseH, 0, Kh, Kl);   // commits Q + K0 as one group

    const int cg = lane >> 2;
    const int ct = lane & 3;

    float m8[8], l8[8];
#pragma unroll
    for (int ss2 = 0; ss2 < 8; ss2++) { m8[ss2] = -1e30f; l8[ss2] = 0.f; }

    for (int tt = 0; tt < 8; tt++) {
        const int st = tt & 1;
        if (tt < 7) {
            scf_fillK(spool, st ^ 1, tid, baseH, tt + 1, Kh, Kl);
            asm volatile("cp.async.wait_group 1;");
        } else {
            asm volatile("cp.async.wait_group 0;");
        }
        __syncthreads();

        __nv_bfloat16* sKh_ = spool + (2 + 2 * st) * SCF_TILE;
        __nv_bfloat16* sKl_ = sKh_ + SCF_TILE;

        float acc[4][4][4];
#pragma unroll
        for (int im = 0; im < 4; im++)
#pragma unroll
            for (int jn = 0; jn < 4; jn++)
#pragma unroll
                for (int qq = 0; qq < 4; qq++) acc[im][jn][qq] = 0.f;

#pragma unroll
        for (int ks = 0; ks < 64; ks += 16) {
            uint32_t fAh[4][4], fAl[4][4], fBh[4][2], fBl[4][2];
#pragma unroll
            for (int mt = 0; mt < 4; mt++) {
                int ra = wm * 64 + mt * 16 + (lane & 15);
                int ca = ks + (lane >> 4) * 8;
                ldsm4(fAh[mt], smem_u32(sQh + ra * 72 + ca));
                ldsm4(fAl[mt], smem_u32(sQl + ra * 72 + ca));
            }
#pragma unroll
            for (int pp = 0; pp < 2; pp++) {
                int rb = wn * 32 + pp * 16 + ((lane >> 4) & 1) * 8 + (lane & 7);
                int cb = ks + ((lane >> 3) & 1) * 8;
                ldsm4(&fBh[2 * pp][0], smem_u32(sKh_ + rb * 72 + cb));
                ldsm4(&fBl[2 * pp][0], smem_u32(sKl_ + rb * 72 + cb));
            }
#pragma unroll
            for (int mt = 0; mt < 4; mt++)
#pragma unroll
                for (int nt = 0; nt < 4; nt++)
                    mma16816(acc[mt][nt], fAh[mt], fBh[nt]);
#pragma unroll
            for (int mt = 0; mt < 4; mt++)
#pragma unroll
                for (int nt = 0; nt < 4; nt++)
                    mma16816(acc[mt][nt], fAh[mt], fBl[nt]);
#pragma unroll
            for (int mt = 0; mt < 4; mt++)
#pragma unroll
                for (int nt = 0; nt < 4; nt++)
                    mma16816(acc[mt][nt], fAl[mt], fBh[nt]);
        }

        // epilogue: mask, write raw S, online row stats over this warp's 32 cols
#pragma unroll
        for (int mt = 0; mt < 4; mt++) {
#pragma unroll
            for (int hrow = 0; hrow < 2; hrow++) {
                int rloc = wm * 64 + mt * 16 + cg + hrow * 8;
                int grow = s0 + rloc;
                const unsigned char* mrow = mask + ((size_t)(bidx * SS + grow)) * SS;
                float rv[8];
#pragma unroll
                for (int nt = 0; nt < 4; nt++) {
                    int col = tt * 128 + wn * 32 + nt * 8 + 2 * ct;
                    float av0 = acc[mt][nt][hrow * 2 + 0] * 0.125f;
                    float av1 = acc[mt][nt][hrow * 2 + 1] * 0.125f;
                    uchar2 mk2 = *(const uchar2*)(mrow + col);
                    if (mk2.x) av0 = -1e30f;
                    if (mk2.y) av1 = -1e30f;
                    rv[nt * 2 + 0] = av0;
                    rv[nt * 2 + 1] = av1;
                    *(float2*)(attn + ((size_t)bhid * SS + grow) * SS + col) = make_float2(av0, av1);
                }
                float tm = rv[0];
#pragma unroll
                for (int uu = 1; uu < 8; uu++) tm = fmaxf(tm, rv[uu]);
                // share tile-max across the 4 lanes of this row (ct lanes)
                tm = fmaxf(tm, __shfl_xor_sync(0xffffffffu, tm, 1));
                tm = fmaxf(tm, __shfl_xor_sync(0xffffffffu, tm, 2));
                float tsum = 0.f;
#pragma unroll
                for (int uu = 0; uu < 8; uu++) tsum += expf(rv[uu] - tm);
                tsum += __shfl_xor_sync(0xffffffffu, tsum, 1);
                tsum += __shfl_xor_sync(0xffffffffu, tsum, 2);
                // online merge into running stats
                int slot = mt * 2 + hrow;
                float nm = fmaxf(m8[slot], tm);
                l8[slot] = l8[slot] * expf(m8[slot] - nm) + tsum * expf(tm - nm);
                m8[slot] = nm;
            }
        }
        __syncthreads();
    }

    // cross-warp reduce of row stats
#pragma unroll
    for (int slot = 0; slot < 8; slot++) {
        int mt = slot >> 1;
        int hrow = slot & 1;
        int rloc = wm * 64 + mt * 16 + cg + hrow * 8;
        if (ct == 0) {
            warpM[wn][rloc] = m8[slot];
            warpL[wn][rloc] = l8[slot];
        }
    }
    __syncthreads();
    if (tid < 128) {
        float fm = warpM[0][tid];
        float fl = warpL[0][tid];
#pragma unroll
        for (int ww = 1; ww < 4; ww++) {
            float m2 = warpM[ww][tid];
            float l2 = warpL[ww][tid];
            float nm = fmaxf(fm, m2);
            fl = fl * expf(fm - nm) + l2 * expf(m2 - nm);
            fm = nm;
        }
        rowM[tid] = fm;
        rowI[tid] = 1.0f / fl;
    }
    __syncthreads();

    // pass 2: normalize strip in place (reads are L2-hot)
    for (int kk = 0; kk < 128; kk++) {
        float rm = rowM[kk];
        float ri = rowI[kk];
        size_t aoff = ((size_t)bhid * SS + s0 + kk) * SS + tid * 4;
        float4 sv = *(const float4*)(attn + aoff);
        sv.x = expf(sv.x - rm) * ri;
        sv.y = expf(sv.y - rm) * ri;
        sv.z = expf(sv.z - rm) * ri;
        sv.w = expf(sv.w - rm) * ri;
        *(float4*)(attn + aoff) = sv;
    }
}

// =============================================================================
// Context: per head, ctx[s,d] = sum_t attn[s,t] * V[t,d].  M=1024,N=64,K=1024.
// Register-prefetched fill + pass-major MMA.
// =============================================================================
__global__ __launch_bounds__(256) void context_tc(
    const float* __restrict__ attn,
    const __nv_bfloat16* __restrict__ Vh, const __nv_bfloat16* __restrict__ Vl,
    __nv_bfloat16* __restrict__ Ch, __nv_bfloat16* __restrict__ Cl)
{
    __shared__ __align__(16) __nv_bfloat16 sPh[128][40];
    __shared__ __align__(16) __nv_bfloat16 sPl[128][40];
    __shared__ __align__(16) __nv_bfloat16 sVh[32][72];
    __shared__ __align__(16) __nv_bfloat16 sVl[32][72];

    const int tid  = threadIdx.x;
    const int lane = tid & 31;
    const int wid  = tid >> 5;
    const int wm   = wid >> 1;   // 0..3
    const int wn   = wid & 1;    // 0..1
    const int bhid = blockIdx.y;
    const int bidx = bhid >> 4;
    const int hidx = bhid & 15;
    const int s0   = blockIdx.x * 128;

    const int prow = tid >> 3;           // attn fill row (with +256 offset rows)
    const int pcol = (tid & 7) * 4;
    const int vrow = tid >> 3;
    const int vcol = (tid & 7) * 8;

    float acc[2][4][4];
#pragma unroll
    for (int im = 0; im < 2; im++)
#pragma unroll
        for (int jn = 0; jn < 4; jn++)
#pragma unroll
            for (int qq = 0; qq < 4; qq++) acc[im][jn][qq] = 0.f;

    // prefetch tile 0
    float4 pf[4];
    uint4 pfvh, pfvl;
#pragma unroll
    for (int qq = 0; qq < 4; qq++)
        pf[qq] = *(const float4*)(attn + ((size_t)bhid * SS + s0 + prow + qq * 32) * SS + pcol);
    {
        size_t offV = ((size_t)bhid * SS + vrow) * DK + vcol;
        pfvh = *(const uint4*)(Vh + offV);
        pfvl = *(const uint4*)(Vl + offV);
    }

    for (int kt = 0; kt < SS; kt += 32) {
        // convert prefetched regs into smem
#pragma unroll
        for (int qq = 0; qq < 4; qq++) {
            int srow = prow + qq * 32;
            __nv_bfloat16 ph0, ph1, ph2, ph3, pl0, pl1, pl2, pl3;
            splitbf(pf[qq].x, ph0, pl0); splitbf(pf[qq].y, ph1, pl1);
            splitbf(pf[qq].z, ph2, pl2); splitbf(pf[qq].w, ph3, pl3);
            *(__nv_bfloat162*)&sPh[srow][pcol]     = __halves2bfloat162(ph0, ph1);
            *(__nv_bfloat162*)&sPh[srow][pcol + 2] = __halves2bfloat162(ph2, ph3);
            *(__nv_bfloat162*)&sPl[srow][pcol]     = __halves2bfloat162(pl0, pl1);
            *(__nv_bfloat162*)&sPl[srow][pcol + 2] = __halves2bfloat162(pl2, pl3);
        }
        *(uint4*)&sVh[vrow][vcol] = pfvh;
        *(uint4*)&sVl[vrow][vcol] = pfvl;
        __syncthreads();

        // prefetch next tile (LDG latency overlaps MMA below)
        if (kt + 32 < SS) {
#pragma unroll
            for (int qq = 0; qq < 4; qq++)
                pf[qq] = *(const float4*)(attn + ((size_t)bhid * SS + s0 + prow + qq * 32) * SS + kt + 32 + pcol);
            size_t offV = ((size_t)bhid * SS + kt + 32 + vrow) * DK + vcol;
            pfvh = *(const uint4*)(Vh + offV);
            pfvl = *(const uint4*)(Vl + offV);
        }

#pragma unroll
        for (int ks = 0; ks < 32; ks += 16) {
            uint32_t fAh[2][4], fAl[2][4], fBh[4][2], fBl[4][2];
#pragma unroll
            for (int mt = 0; mt < 2; mt++) {
                int ra = wm * 32 + mt * 16 + (lane & 15);
                int ca = ks + (lane >> 4) * 8;
                ldsm4(fAh[mt], smem_u32(&sPh[ra][ca]));
                ldsm4(fAl[mt], smem_u32(&sPl[ra][ca]));
            }
#pragma unroll
            for (int pp = 0; pp < 2; pp++) {
                int rb = ks + ((lane >> 3) & 1) * 8 + (lane & 7);
                int cb = wn * 32 + pp * 16 + (lane >> 4) * 8;
                ldsm4t(&fBh[2 * pp][0], smem_u32(&sVh[rb][cb]));
                ldsm4t(&fBl[2 * pp][0], smem_u32(&sVl[rb][cb]));
            }
#pragma unroll
            for (int mt = 0; mt < 2; mt++)
#pragma unroll
                for (int nt = 0; nt < 4; nt++)
                    mma16816(acc[mt][nt], fAh[mt], fBh[nt]);
#pragma unroll
            for (int mt = 0; mt < 2; mt++)
#pragma unroll
                for (int nt = 0; nt < 4; nt++)
                    mma16816(acc[mt][nt], fAh[mt], fBl[nt]);
#pragma unroll
            for (int mt = 0; mt < 2; mt++)
#pragma unroll
                for (int nt = 0; nt < 4; nt++)
                    mma16816(acc[mt][nt], fAl[mt], fBh[nt]);
        }
        __syncthreads();
    }

    const int cg = lane >> 2;
    const int ct = lane & 3;
#pragma unroll
    for (int mt = 0; mt < 2; mt++)
#pragma unroll
        for (int nt = 0; nt < 4; nt++) {
            int dd = wn * 32 + nt * 8 + 2 * ct;
#pragma unroll
            for (int hrow = 0; hrow < 2; hrow++) {
                int mmv = s0 + wm * 32 + mt * 16 + cg + hrow * 8;
                float ov0 = acc[mt][nt][hrow * 2 + 0];
                float ov1 = acc[mt][nt][hrow * 2 + 1];
                size_t oidx = ((size_t)(bidx * SS + mmv)) * DD + hidx * 64 + dd;
                __nv_bfloat16 zh0, zl0, zh1, zl1;
                splitbf(ov0, zh0, zl0);
                splitbf(ov1, zh1, zl1);
                *(__nv_bfloat162*)(Ch + oidx) = __halves2bfloat162(zh0, zh1);
                *(__nv_bfloat162*)(Cl + oidx) = __halves2bfloat162(zl0, zl1);
            }
        }
}

// =============================================================================
// LayerNorm: one block per row of 1024.
// =============================================================================
__global__ __launch_bounds__(256) void ln_kernel(
    const float* __restrict__ xin, const float* __restrict__ gamma,
    const float* __restrict__ beta, float* __restrict__ outp)
{
    __shared__ float sredA[8];
    __shared__ float sredB[8];
    const int row = blockIdx.x;
    const int tt = threadIdx.x;
    float4 lv = *(const float4*)(xin + (size_t)row * DD + tt * 4);

    float s1 = lv.x + lv.y + lv.z + lv.w;
    float s2 = lv.x * lv.x + lv.y * lv.y + lv.z * lv.z + lv.w * lv.w;
    s1 = wredSum(s1);
    s2 = wredSum(s2);
    if ((tt & 31) == 0) { sredA[tt >> 5] = s1; sredB[tt >> 5] = s2; }
    __syncthreads();
    if (tt < 32) {
        float ta = (tt < 8) ? sredA[tt] : 0.f;
        float tb = (tt < 8) ? sredB[tt] : 0.f;
        ta = wredSum(ta);
        tb = wredSum(tb);
        if (tt == 0) { sredA[0] = ta; sredB[0] = tb; }
    }
    __syncthreads();
    float mu  = sredA[0] * (1.0f / 1024.0f);
    float var = sredB[0] * (1.0f / 1024.0f) - mu * mu;
    float inv = rsqrtf(var + 1e-6f);

    float4 gv4 = *(const float4*)(gamma + tt * 4);
    float4 bv4 = *(const float4*)(beta + tt * 4);
    float4 ov4;
    ov4.x = (lv.x - mu) * inv * gv4.x + bv4.x;
    ov4.y = (lv.y - mu) * inv * gv4.y + bv4.y;
    ov4.z = (lv.z - mu) * inv * gv4.z + bv4.z;
    ov4.w = (lv.w - mu) * inv * gv4.w + bv4.w;
    *(float4*)(outp + (size_t)row * DD + tt * 4) = ov4;
}

// =============================================================================
extern "C" void kernel_launch(void* const* d_in, const int* in_sizes, int n_in,
                              void* d_out, int out_size)
{
    const float* in_q = (const float*)d_in[0];
    const float* in_k = (const float*)d_in[1];
    const float* in_v = (const float*)d_in[2];
    const unsigned char* in_mask = (const unsigned char*)d_in[3];
    const float* Wq   = (const float*)d_in[4];
    const float* bq   = (const float*)d_in[5];
    const float* Wk   = (const float*)d_in[6];
    const float* bk   = (const float*)d_in[7];
    const float* Wv   = (const float*)d_in[8];
    const float* bvv  = (const float*)d_in[9];
    const float* Wo   = (const float*)d_in[10];
    const float* bo   = (const float*)d_in[11];
    const float* ln_g = (const float*)d_in[12];
    const float* ln_b = (const float*)d_in[13];

    float* out_norm = (float*)d_out;
    float* attn = (float*)d_out + (size_t)MM * DD;

    __nv_bfloat16 *pqh, *pql, *pkh, *pkl, *pvh, *pvl;
    __nv_bfloat16 *pwqh, *pwql, *pwkh, *pwkl, *pwvh, *pwvl, *pwoh, *pwol;
    __nv_bfloat16 *pQh, *pQl, *pKh, *pKl, *pVh, *pVl, *pCh, *pCl;
    float *pX;
    cudaGetSymbolAddress((void**)&pqh, g_qh);
    cudaGetSymbolAddress((void**)&pql, g_ql);
    cudaGetSymbolAddress((void**)&pkh, g_kh);
    cudaGetSymbolAddress((void**)&pkl, g_kl);
    cudaGetSymbolAddress((void**)&pvh, g_vh);
    cudaGetSymbolAddress((void**)&pvl, g_vl);
    cudaGetSymbolAddress((void**)&pwqh, g_wqh);
    cudaGetSymbolAddress((void**)&pwql, g_wql);
    cudaGetSymbolAddress((void**)&pwkh, g_wkh);
    cudaGetSymbolAddress((void**)&pwkl, g_wkl);
    cudaGetSymbolAddress((void**)&pwvh, g_wvh);
    cudaGetSymbolAddress((void**)&pwvl, g_wvl);
    cudaGetSymbolAddress((void**)&pwoh, g_woh);
    cudaGetSymbolAddress((void**)&pwol, g_wol);
    cudaGetSymbolAddress((void**)&pQh, g_Qh);
    cudaGetSymbolAddress((void**)&pQl, g_Ql);
    cudaGetSymbolAddress((void**)&pKh, g_Kh);
    cudaGetSymbolAddress((void**)&pKl, g_Kl);
    cudaGetSymbolAddress((void**)&pVh, g_Vh);
    cudaGetSymbolAddress((void**)&pVl, g_Vl);
    cudaGetSymbolAddress((void**)&pCh, g_Ch);
    cudaGetSymbolAddress((void**)&pCl, g_Cl);
    cudaGetSymbolAddress((void**)&pX,  g_x);

    cudaFuncSetAttribute(gemm_tc<1, 0>, cudaFuncAttributeMaxDynamicSharedMemorySize, 81920);
    cudaFuncSetAttribute(gemm_tc<0, 1>, cudaFuncAttributeMaxDynamicSharedMemorySize, 81920);
    cudaFuncSetAttribute(scores_fused, cudaFuncAttributeMaxDynamicSharedMemorySize, 110592);

    SplitArgs sa;
    sa.src[0] = in_q;  sa.dsth[0] = pqh;  sa.dstl[0] = pql;
    sa.src[1] = in_k;  sa.dsth[1] = pkh;  sa.dstl[1] = pkl;
    sa.src[2] = in_v;  sa.dsth[2] = pvh;  sa.dstl[2] = pvl;
    sa.src[3] = in_q;  sa.dsth[3] = pqh;  sa.dstl[3] = pql;  // unused
    split_multi<3, MM * DD><<<2048, 256>>>(sa);

    SplitArgs sw;
    sw.src[0] = Wq;  sw.dsth[0] = pwqh;  sw.dstl[0] = pwql;
    sw.src[1] = Wk;  sw.dsth[1] = pwkh;  sw.dstl[1] = pwkl;
    sw.src[2] = Wv;  sw.dsth[2] = pwvh;  sw.dstl[2] = pwvl;
    sw.src[3] = Wo;  sw.dsth[3] = pwoh;  sw.dstl[3] = pwol;
    split_multi<4, DD * DD><<<2048, 256>>>(sw);

    dim3 gGemm(DD / 128, MM / 128);   // (8, 32)
    gemm_tc<1, 0><<<gGemm, 256, 81920>>>(pqh, pql, pwqh, pwql, bq, nullptr, pQh, pQl, nullptr);
    gemm_tc<1, 0><<<gGemm, 256, 81920>>>(pkh, pkl, pwkh, pwkl, bk, nullptr, pKh, pKl, nullptr);
    gemm_tc<1, 0><<<gGemm, 256, 81920>>>(pvh, pvl, pwvh, pwvl, bvv, nullptr, pVh, pVl, nullptr);

    dim3 gSc(SS / 128, BB * HH);      // (8, 64)
    scores_fused<<<gSc, 256, 110592>>>(pQh, pQl, pKh, pKl, in_mask, attn);

    dim3 gCtx(SS / 128, BB * HH);     // (8, 64)
    context_tc<<<gCtx, 256>>>(attn, pVh, pVl, pCh, pCl);

    gemm_tc<0, 1><<<gGemm, 256, 81920>>>(pCh, pCl, pwoh, pwol, bo, in_v, nullptr, nullptr, pX);

    ln_kernel<<<MM, 256>>>(pX, ln_g, ln_b, out_norm);
}